// round 12
// baseline (speedup 1.0000x reference)
#include <cuda_runtime.h>
#include <cstdint>

#define Tn 512
#define Bn 128
#define Hn 256
#define Gn 1024
#define NBLK 256

typedef unsigned long long u64t;

// ---------------- device scratch ----------------
__device__ float g_pre0[(size_t)Tn * Gn * Bn];   // [t][gatecol][b]
__device__ float g_h0[2][Hn * Bn];               // [pp][h][b]
__device__ float g_h1[2][Hn * Bn];
__device__ volatile unsigned g_bar_gen = 0;      // init barrier (monotonic)
__device__ unsigned g_bar_cnt = 0;
__device__ __align__(128) unsigned g_cnt0;       // h0 epoch counter
__device__ __align__(128) unsigned g_gen0;       // h0 generation (monotonic)
__device__ __align__(128) unsigned g_cnt1;       // h1 epoch counter
__device__ __align__(128) unsigned g_gen1;       // h1 generation (monotonic)

__device__ __forceinline__ float fsig(float x) {
    return __fdividef(1.0f, 1.0f + __expf(-x));
}
__device__ __forceinline__ float ftanh2(float x) {
    float e = __expf(2.0f * x);
    return 1.0f - __fdividef(2.0f, e + 1.0f);
}
// init-only grid barrier
__device__ __forceinline__ void grid_barrier() {
    __syncthreads();
    if (threadIdx.x == 0) {
        asm volatile("fence.acq_rel.gpu;" ::: "memory");
        unsigned gen = g_bar_gen;
        if (atomicAdd(&g_bar_cnt, 1u) == (unsigned)(NBLK - 1)) {
            g_bar_cnt = 0u;
            asm volatile("fence.acq_rel.gpu;" ::: "memory");
            g_bar_gen = gen + 1u;
        } else {
            while (g_bar_gen == gen) { __nanosleep(20); }
            asm volatile("fence.acq_rel.gpu;" ::: "memory");
        }
    }
    __syncthreads();
}
// t0 waits until *genp >= target (signed distance), then acquire; all sync.
__device__ __forceinline__ void gen_wait(unsigned* genp, unsigned target) {
    if (threadIdx.x == 0) {
        while ((int)(__ldcg(genp) - target) < 0) { __nanosleep(20); }
        asm volatile("fence.acq_rel.gpu;" ::: "memory");
    }
    __syncthreads();
}
// all threads' prior stores -> syncthreads -> t0 release-arrive; last flips gen.
__device__ __forceinline__ void gen_arrive(unsigned* cntp, unsigned* genp,
                                           unsigned next) {
    __syncthreads();
    if (threadIdx.x == 0) {
        asm volatile("fence.acq_rel.gpu;" ::: "memory");
        if (atomicAdd(cntp, 1u) == (unsigned)(NBLK - 1)) {
            *cntp = 0u;
            asm volatile("fence.acq_rel.gpu;" ::: "memory");
            __stcg(genp, next);
        }
    }
}
__device__ __forceinline__ void ffma2(u64t& d, u64t a, u64t b) {
    asm volatile("fma.rn.f32x2 %0, %1, %2, %0;" : "+l"(d) : "l"(a), "l"(b));
}
__device__ __forceinline__ u64t dup2(float w) {
    u64t r;
    asm("mov.b64 %0, {%1, %1};" : "=l"(r) : "f"(w));
    return r;
}
__device__ __forceinline__ u64t pack2(float a, float b) {
    u64t r;
    asm("mov.b64 %0, {%1, %2};" : "=l"(r) : "f"(a), "f"(b));
    return r;
}
__device__ __forceinline__ float2 unpack2(u64t v) {
    float2 r;
    asm("mov.b64 {%0, %1}, %2;" : "=f"(r.x), "=f"(r.y) : "l"(v));
    return r;
}
__device__ __forceinline__ u64t addx2(u64t a, u64t b) {
    u64t r;
    asm("add.rn.f32x2 %0, %1, %2;" : "=l"(r) : "l"(a), "l"(b));
    return r;
}
__device__ __forceinline__ void cp16(void* dst, const float* src) {
    unsigned d = (unsigned)__cvta_generic_to_shared(dst);
    asm volatile("cp.async.cg.shared.global [%0], [%1], 16;" :: "r"(d), "l"(src));
}

// ---------------------------------------------------------------------------
// Precompute (unchanged): pre0[t][g][b]; tile 128g x 128b, K-chunk 64.
// ---------------------------------------------------------------------------
#define PRE_SMEM 67584

__global__ __launch_bounds__(256, 2) void precompute_kernel(
    const float* __restrict__ x, const float* __restrict__ W_ih,
    const float* __restrict__ b_ih, const float* __restrict__ b_hh)
{
    extern __shared__ __align__(16) char psm[];
    u64t*  Xs = reinterpret_cast<u64t*>(psm);            // [kk][66]
    float* Ws = reinterpret_cast<float*>(psm + 33792);   // [kk][132]
    const int gt = blockIdx.x;
    const int t  = blockIdx.y;
    const int tid = threadIdx.x;
    const int gy = tid >> 4;
    const int bx = tid & 15;

    const float* xb = x + (size_t)t * Bn * Hn;
    const float* wb = W_ih + (size_t)(gt * 128) * Hn;

    u64t acc[8][4];
#pragma unroll
    for (int i = 0; i < 8; i++)
#pragma unroll
        for (int j = 0; j < 4; j++) acc[i][j] = 0ull;

    for (int kc = 0; kc < Hn; kc += 64) {
        {
            int bp = tid & 63;
            int kq = (tid >> 6) * 16;
            const float* r0 = xb + (size_t)(2 * bp) * Hn + kc + kq;
            const float* r1 = r0 + Hn;
#pragma unroll
            for (int q = 0; q < 4; q++) {
                float4 a = *reinterpret_cast<const float4*>(r0 + q * 4);
                float4 b4 = *reinterpret_cast<const float4*>(r1 + q * 4);
                Xs[(kq + q * 4 + 0) * 66 + bp] = pack2(a.x, b4.x);
                Xs[(kq + q * 4 + 1) * 66 + bp] = pack2(a.y, b4.y);
                Xs[(kq + q * 4 + 2) * 66 + bp] = pack2(a.z, b4.z);
                Xs[(kq + q * 4 + 3) * 66 + bp] = pack2(a.w, b4.w);
            }
        }
        {
            int g   = tid & 127;
            int kq2 = (tid >> 7) * 32;
            const float* wr = wb + (size_t)g * Hn + kc + kq2;
#pragma unroll
            for (int q = 0; q < 8; q++) {
                float4 wv = *reinterpret_cast<const float4*>(wr + q * 4);
                Ws[(kq2 + q * 4 + 0) * 132 + g] = wv.x;
                Ws[(kq2 + q * 4 + 1) * 132 + g] = wv.y;
                Ws[(kq2 + q * 4 + 2) * 132 + g] = wv.z;
                Ws[(kq2 + q * 4 + 3) * 132 + g] = wv.w;
            }
        }
        __syncthreads();
#pragma unroll
        for (int kk = 0; kk < 64; kk++) {
            ulonglong2 h01 = *reinterpret_cast<const ulonglong2*>(&Xs[kk * 66 + bx * 4]);
            ulonglong2 h23 = *reinterpret_cast<const ulonglong2*>(&Xs[kk * 66 + bx * 4 + 2]);
            float4 wa = *reinterpret_cast<const float4*>(&Ws[kk * 132 + gy * 8]);
            float4 wbv = *reinterpret_cast<const float4*>(&Ws[kk * 132 + gy * 8 + 4]);
            u64t wd[8] = { dup2(wa.x), dup2(wa.y), dup2(wa.z), dup2(wa.w),
                           dup2(wbv.x), dup2(wbv.y), dup2(wbv.z), dup2(wbv.w) };
            u64t hh[4] = { h01.x, h01.y, h23.x, h23.y };
#pragma unroll
            for (int gi = 0; gi < 8; gi++)
#pragma unroll
                for (int j = 0; j < 4; j++)
                    ffma2(acc[gi][j], hh[j], wd[gi]);
        }
        __syncthreads();
    }
#pragma unroll
    for (int gi = 0; gi < 8; gi++) {
        int g = gt * 128 + gy * 8 + gi;
        float bias = __ldg(b_ih + g) + __ldg(b_hh + g);
        float2 u0 = unpack2(acc[gi][0]);
        float2 u1 = unpack2(acc[gi][1]);
        float2 u2 = unpack2(acc[gi][2]);
        float2 u3 = unpack2(acc[gi][3]);
        float* op = g_pre0 + (size_t)t * (Gn * Bn) + (size_t)g * Bn + bx * 8;
        *reinterpret_cast<float4*>(op) =
            make_float4(u0.x + bias, u0.y + bias, u1.x + bias, u1.y + bias);
        *reinterpret_cast<float4*>(op + 4) =
            make_float4(u2.x + bias, u2.y + bias, u3.x + bias, u3.y + bias);
    }
}

// ---------------------------------------------------------------------------
// Persistent skewed recurrence, split-barrier. 256 CTAs x 256 threads.
// CTA: bq = blk&3 (batch quarter 32), cg = blk>>2 (4 h-cols, both layers).
// Warps (8): bsel = w&1 (16-batch), kshi = w>>1 (64-K slice).
// Lanes: cs = lane&7 (2 col-pairs), kslo = lane>>3 (16-K sub-slice).
// gen0 flips after EW0 publishes h0[i] (mid-iteration).
// gen1 flips after EW1 publishes h1[i-1] (end of iteration).
// smem: WA 32768 | WB 16384 | stageA 32768 (partials overlay) | stageB 32768
// ---------------------------------------------------------------------------
#define SM_WA    0
#define SM_WB    32768
#define SM_STAGE 49152
#define SM_STB_OFF 32768
#define SMEM_TOTAL 114688

__global__ __launch_bounds__(256, 2) void lstm_persistent(
    const float* __restrict__ W_ih, const float* __restrict__ W_hh,
    const float* __restrict__ b_ih, const float* __restrict__ b_hh,
    float* __restrict__ out)
{
    extern __shared__ __align__(16) char smraw[];
    char* smWA   = smraw + SM_WA;
    char* smWB   = smraw + SM_WB;
    char* stage  = smraw + SM_STAGE;          // stage A; stage B = +32768
    char* partc  = smraw + SM_STAGE;          // partials overlay stage A

    const int tid  = threadIdx.x;
    const int blk  = blockIdx.x;
    const int bq   = blk & 3;
    const int cg   = blk >> 2;
    const int w    = tid >> 5;
    const int lane = tid & 31;
    const int bsel = w & 1;
    const int kshi = w >> 1;          // 0..3
    const int cs   = lane & 7;
    const int kslo = lane >> 3;       // 0..3

    // bases must be read before any flip (flips happen after init barrier)
    const unsigned base0 = __ldcg(&g_gen0);
    const unsigned base1 = __ldcg(&g_gen1);

    // ---- weights into smem (plain floats, once) ----
    {
        int p  = tid & 15;
        int kg = tid >> 4;            // 0..15 -> 16 k each
        int gc = (p >> 2) * Hn + cg * 4 + (p & 3);
        const float* wh0 = W_hh + (size_t)gc * Hn;
        const float* wi1 = W_ih + (size_t)Gn * Hn + (size_t)gc * Hn;
        float* WA = reinterpret_cast<float*>(smWA);
#pragma unroll
        for (int j = 0; j < 16; j++) {
            int k = kg * 16 + j;
            WA[k * 32 + p * 2 + 0] = __ldg(wh0 + k);
            WA[k * 32 + p * 2 + 1] = __ldg(wi1 + k);
        }
        int c   = tid & 7;
        int kg2 = tid >> 3;           // 0..31 -> 8 k each
        int gcA = ((2 * c) >> 2) * Hn + cg * 4 + ((2 * c) & 3);
        int gcB = ((2 * c + 1) >> 2) * Hn + cg * 4 + ((2 * c + 1) & 3);
        const float* wh1a = W_hh + (size_t)Gn * Hn + (size_t)gcA * Hn;
        const float* wh1b = W_hh + (size_t)Gn * Hn + (size_t)gcB * Hn;
        float* WB = reinterpret_cast<float*>(smWB);
#pragma unroll
        for (int j = 0; j < 8; j++) {
            int k = kg2 * 8 + j;
            WB[k * 16 + c * 2 + 0] = __ldg(wh1a + k);
            WB[k * 16 + c * 2 + 1] = __ldg(wh1b + k);
        }
    }
    // elementwise identity (EW0: tid<128, EW1: tid>=128)
    const int hcl = (tid >> 5) & 3;
    const int bl  = tid & 31;
    const int hcol = cg * 4 + hcl;
    const int b = bq * 32 + bl;
    float b1s[4];
#pragma unroll
    for (int g = 0; g < 4; g++)
        b1s[g] = __ldg(b_ih + Gn + g * Hn + hcol) + __ldg(b_hh + Gn + g * Hn + hcol);

    // per-warp staging base (4 blocks of 1024B, seg-swizzled)
    char* myst = stage + w * 4096;

    // zero init h ping-pong buffers (256 CTAs x 256 threads = 65536)
    {
        int idx = blk * 256 + tid;
        reinterpret_cast<float*>(g_h0)[idx] = 0.f;
        reinterpret_cast<float*>(g_h1)[idx] = 0.f;
    }
    float creg = 0.f;

    const size_t OUT_H = (size_t)Tn * Bn * Hn;
    const size_t OUT_C = OUT_H + 2 * (size_t)Bn * Hn;

    grid_barrier();   // init visible; bases stable before any flips

    // swizzled read pointers (stage A; stage B = +SM_STB_OFF)
    const char* p0 = myst + kslo * 1024 + (((0 + kslo) & 3) << 4);
    const char* p1 = myst + kslo * 1024 + (((1 + kslo) & 3) << 4);
    const char* p2 = myst + kslo * 1024 + (((2 + kslo) & 3) << 4);
    const char* p3 = myst + kslo * 1024 + (((3 + kslo) & 3) << 4);

    for (int i = 0; i <= Tn; i++) {
        const int rslot = (i & 1) ^ 1;
        const int wslot = i & 1;

        // ===== wait: h0[i-1] published by all CTAs =====
        gen_wait(&g_gen0, base0 + (unsigned)i);

        const float* hA = g_h0[rslot];
        // ---- stage A (h0 slice), swizzled ----
#pragma unroll
        for (int j = 0; j < 8; j++) {
            int f = lane + j * 32;
            int ksb = f >> 6, rem = f & 63;
            int krow = rem >> 2, seg = rem & 3;
            int k = kshi * 64 + ksb * 16 + krow;
            size_t so = (size_t)k * Bn + bq * 32 + bsel * 16 + seg * 4;
            cp16(myst + ksb * 1024 + krow * 64 + (((seg + ksb) & 3) << 4), hA + so);
        }
        asm volatile("cp.async.commit_group;");

        // prefetch pre0 gates (EW0 operand) while staging flies
        float pg[4] = {0.f, 0.f, 0.f, 0.f};
        if (tid < 128 && i < Tn) {
            const float* pb = g_pre0 + (size_t)i * (Gn * Bn);
#pragma unroll
            for (int g = 0; g < 4; g++)
                pg[g] = __ldg(pb + (size_t)(g * Hn + hcol) * Bn + b);
        }

        u64t acc[4][8];
#pragma unroll
        for (int r = 0; r < 4; r++)
#pragma unroll
            for (int j = 0; j < 8; j++) acc[r][j] = 0ull;

        asm volatile("cp.async.wait_group 0;");
        __syncwarp();
        // ===== phase A: L0-rec + L1-input on h0 slice =====
        {
            const char* wp = smWA + (size_t)(kshi * 64 + kslo * 16) * 128 + cs * 16;
#pragma unroll
            for (int u = 0; u < 16; u++) {
                ulonglong2 h0v = *reinterpret_cast<const ulonglong2*>(p0 + u * 64);
                ulonglong2 h1v = *reinterpret_cast<const ulonglong2*>(p1 + u * 64);
                ulonglong2 h2v = *reinterpret_cast<const ulonglong2*>(p2 + u * 64);
                ulonglong2 h3v = *reinterpret_cast<const ulonglong2*>(p3 + u * 64);
                float4 wv = *reinterpret_cast<const float4*>(wp);
                u64t w0a = dup2(wv.x), w1a = dup2(wv.y);
                u64t w0b = dup2(wv.z), w1b = dup2(wv.w);
                u64t hh[8] = {h0v.x, h0v.y, h1v.x, h1v.y, h2v.x, h2v.y, h3v.x, h3v.y};
#pragma unroll
                for (int j = 0; j < 8; j++) {
                    ffma2(acc[0][j], hh[j], w0a);
                    ffma2(acc[2][j], hh[j], w1a);
                    ffma2(acc[1][j], hh[j], w0b);
                    ffma2(acc[3][j], hh[j], w1b);
                }
                wp += 128;
            }
        }
        // ---- reduce L0 accumulators across kslo ----
#pragma unroll
        for (int r = 0; r < 2; r++)
#pragma unroll
            for (int j = 0; j < 8; j++) {
                u64t v = acc[r][j];
                v = addx2(v, (u64t)__shfl_xor_sync(0xFFFFFFFFu, v, 8));
                v = addx2(v, (u64t)__shfl_xor_sync(0xFFFFFFFFu, v, 16));
                acc[r][j] = v;
            }
        __syncthreads();   // all warps done reading stage A (partials overlay)
        if (kslo == 0) {
#pragma unroll
            for (int r = 0; r < 2; r++) {
                int row = 2 * cs + r;
                char* pb = partc + row * 528 + kshi * 128 + bsel * 64;
                reinterpret_cast<ulonglong2*>(pb)[0] = make_ulonglong2(acc[r][0], acc[r][1]);
                reinterpret_cast<ulonglong2*>(pb)[1] = make_ulonglong2(acc[r][2], acc[r][3]);
                reinterpret_cast<ulonglong2*>(pb)[2] = make_ulonglong2(acc[r][4], acc[r][5]);
                reinterpret_cast<ulonglong2*>(pb)[3] = make_ulonglong2(acc[r][6], acc[r][7]);
            }
        }
        __syncthreads();
        // ===== EW0: publish h0[i] NOW =====
        if (tid < 128 && i < Tn) {
            float s[4];
#pragma unroll
            for (int g = 0; g < 4; g++) {
                const float* pr = reinterpret_cast<const float*>(
                    partc + (g * 4 + hcl) * 528 + bl * 4);
                s[g] = pg[g] + pr[0] + pr[32] + pr[64] + pr[96];
            }
            float cn = fsig(s[1]) * creg + fsig(s[0]) * ftanh2(s[2]);
            creg = cn;
            float hn = fsig(s[3]) * ftanh2(cn);
            __stcg(&g_h0[wslot][hcol * Bn + b], hn);
            if (i == Tn - 1) {
                out[OUT_H + (size_t)b * Hn + hcol] = hn;
                out[OUT_C + (size_t)b * Hn + hcol] = cn;
            }
        }
        gen_arrive(&g_cnt0, &g_gen0, base0 + (unsigned)(i + 1));

        // ===== wait: h1[i-2] published by all CTAs =====
        gen_wait(&g_gen1, base1 + (unsigned)(i >= 1 ? i - 1 : 0));

        const float* hB = g_h1[rslot];
        // ---- stage B (h1 slice), swizzled ----
#pragma unroll
        for (int j = 0; j < 8; j++) {
            int f = lane + j * 32;
            int ksb = f >> 6, rem = f & 63;
            int krow = rem >> 2, seg = rem & 3;
            int k = kshi * 64 + ksb * 16 + krow;
            size_t so = (size_t)k * Bn + bq * 32 + bsel * 16 + seg * 4;
            cp16(myst + SM_STB_OFF + ksb * 1024 + krow * 64 + (((seg + ksb) & 3) << 4),
                 hB + so);
        }
        asm volatile("cp.async.commit_group;");
        asm volatile("cp.async.wait_group 0;");
        __syncwarp();
        // ===== phase B: L1-rec on h1 slice (accumulate into L1 accs) =====
        {
            const char* wp = smWB + (size_t)(kshi * 64 + kslo * 16) * 64 + cs * 8;
#pragma unroll
            for (int u = 0; u < 16; u++) {
                ulonglong2 h0v = *reinterpret_cast<const ulonglong2*>(p0 + SM_STB_OFF + u * 64);
                ulonglong2 h1v = *reinterpret_cast<const ulonglong2*>(p1 + SM_STB_OFF + u * 64);
                ulonglong2 h2v = *reinterpret_cast<const ulonglong2*>(p2 + SM_STB_OFF + u * 64);
                ulonglong2 h3v = *reinterpret_cast<const ulonglong2*>(p3 + SM_STB_OFF + u * 64);
                float2 wv = *reinterpret_cast<const float2*>(wp);
                u64t w2a = dup2(wv.x), w2b = dup2(wv.y);
                u64t hh[8] = {h0v.x, h0v.y, h1v.x, h1v.y, h2v.x, h2v.y, h3v.x, h3v.y};
#pragma unroll
                for (int j = 0; j < 8; j++) {
                    ffma2(acc[2][j], hh[j], w2a);
                    ffma2(acc[3][j], hh[j], w2b);
                }
                wp += 64;
            }
        }
        // ---- reduce L1 accumulators across kslo ----
#pragma unroll
        for (int r = 2; r < 4; r++)
#pragma unroll
            for (int j = 0; j < 8; j++) {
                u64t v = acc[r][j];
                v = addx2(v, (u64t)__shfl_xor_sync(0xFFFFFFFFu, v, 8));
                v = addx2(v, (u64t)__shfl_xor_sync(0xFFFFFFFFu, v, 16));
                acc[r][j] = v;
            }
        if (kslo == 0) {
#pragma unroll
            for (int r = 2; r < 4; r++) {
                int row = 16 + 2 * cs + (r - 2);
                char* pb = partc + row * 528 + kshi * 128 + bsel * 64;
                reinterpret_cast<ulonglong2*>(pb)[0] = make_ulonglong2(acc[r][0], acc[r][1]);
                reinterpret_cast<ulonglong2*>(pb)[1] = make_ulonglong2(acc[r][2], acc[r][3]);
                reinterpret_cast<ulonglong2*>(pb)[2] = make_ulonglong2(acc[r][4], acc[r][5]);
                reinterpret_cast<ulonglong2*>(pb)[3] = make_ulonglong2(acc[r][6], acc[r][7]);
            }
        }
        __syncthreads();
        // ===== EW1: publish h1[i-1] =====
        if (tid >= 128 && i >= 1) {
            const int t1 = i - 1;
            float s[4];
#pragma unroll
            for (int g = 0; g < 4; g++) {
                const float* pr = reinterpret_cast<const float*>(
                    partc + (16 + g * 4 + hcl) * 528 + bl * 4);
                s[g] = b1s[g] + pr[0] + pr[32] + pr[64] + pr[96];
            }
            float cn = fsig(s[1]) * creg + fsig(s[0]) * ftanh2(s[2]);
            creg = cn;
            float hn = fsig(s[3]) * ftanh2(cn);
            __stcg(&g_h1[wslot][hcol * Bn + b], hn);
            out[(size_t)t1 * (Bn * Hn) + (size_t)b * Hn + hcol] = hn;
            if (i == Tn) {
                out[OUT_H + (size_t)Bn * Hn + (size_t)b * Hn + hcol] = hn;
                out[OUT_C + (size_t)Bn * Hn + (size_t)b * Hn + hcol] = cn;
            }
        }
        gen_arrive(&g_cnt1, &g_gen1, base1 + (unsigned)i);
    }
}

extern "C" void kernel_launch(void* const* d_in, const int* in_sizes, int n_in,
                              void* d_out, int out_size) {
    (void)in_sizes; (void)n_in; (void)out_size;
    const float* x    = (const float*)d_in[0];
    const float* W_ih = (const float*)d_in[1];
    const float* W_hh = (const float*)d_in[2];
    const float* b_ih = (const float*)d_in[3];
    const float* b_hh = (const float*)d_in[4];
    float* out = (float*)d_out;

    cudaFuncSetAttribute(precompute_kernel,
                         cudaFuncAttributeMaxDynamicSharedMemorySize, PRE_SMEM);
    cudaFuncSetAttribute(lstm_persistent,
                         cudaFuncAttributeMaxDynamicSharedMemorySize, SMEM_TOTAL);

    dim3 gPre(8, 512);
    precompute_kernel<<<gPre, 256, PRE_SMEM>>>(x, W_ih, b_ih, b_hh);
    lstm_persistent<<<NBLK, 256, SMEM_TOTAL>>>(W_ih, W_hh, b_ih, b_hh, out);
}

// round 14
// speedup vs baseline: 1.1597x; 1.1597x over previous
#include <cuda_runtime.h>
#include <cstdint>

#define Tn 512
#define Bn 128
#define Hn 256
#define Gn 1024
#define NBLK 256

typedef unsigned long long u64t;

// ---------------- device scratch ----------------
__device__ float g_pre0[(size_t)Tn * Gn * Bn];   // [t][gatecol][b]
__device__ float g_h0[2][Hn * Bn];               // [pp][h][b]
__device__ float g_h1[2][Hn * Bn];
__device__ volatile unsigned g_bar_gen = 0;
__device__ unsigned g_bar_cnt = 0;

__device__ __forceinline__ float fsig(float x) {
    return __fdividef(1.0f, 1.0f + __expf(-x));
}
__device__ __forceinline__ float ftanh2(float x) {
    float e = __expf(2.0f * x);
    return 1.0f - __fdividef(2.0f, e + 1.0f);
}
// grid barrier: one gpu fence by t0 per CTA (proven-cheap single-poller form)
__device__ __forceinline__ void grid_barrier() {
    __syncthreads();
    if (threadIdx.x == 0) {
        asm volatile("fence.acq_rel.gpu;" ::: "memory");
        unsigned gen = g_bar_gen;
        if (atomicAdd(&g_bar_cnt, 1u) == (unsigned)(NBLK - 1)) {
            g_bar_cnt = 0u;
            asm volatile("fence.acq_rel.gpu;" ::: "memory");
            g_bar_gen = gen + 1u;
        } else {
            while (g_bar_gen == gen) { __nanosleep(20); }
            asm volatile("fence.acq_rel.gpu;" ::: "memory");
        }
    }
    __syncthreads();
}
__device__ __forceinline__ void ffma2(u64t& d, u64t a, u64t b) {
    asm volatile("fma.rn.f32x2 %0, %1, %2, %0;" : "+l"(d) : "l"(a), "l"(b));
}
__device__ __forceinline__ u64t dup2(float w) {
    u64t r;
    asm("mov.b64 %0, {%1, %1};" : "=l"(r) : "f"(w));
    return r;
}
__device__ __forceinline__ u64t pack2(float a, float b) {
    u64t r;
    asm("mov.b64 %0, {%1, %2};" : "=l"(r) : "f"(a), "f"(b));
    return r;
}
__device__ __forceinline__ float2 unpack2(u64t v) {
    float2 r;
    asm("mov.b64 {%0, %1}, %2;" : "=f"(r.x), "=f"(r.y) : "l"(v));
    return r;
}
__device__ __forceinline__ u64t addx2(u64t a, u64t b) {
    u64t r;
    asm("add.rn.f32x2 %0, %1, %2;" : "=l"(r) : "l"(a), "l"(b));
    return r;
}
__device__ __forceinline__ void cp16(void* dst, const float* src) {
    unsigned d = (unsigned)__cvta_generic_to_shared(dst);
    asm volatile("cp.async.cg.shared.global [%0], [%1], 16;" :: "r"(d), "l"(src));
}

// ---------------------------------------------------------------------------
// Precompute (unchanged): pre0[t][g][b]; tile 128g x 128b, K-chunk 64.
// ---------------------------------------------------------------------------
#define PRE_SMEM 67584

__global__ __launch_bounds__(256, 2) void precompute_kernel(
    const float* __restrict__ x, const float* __restrict__ W_ih,
    const float* __restrict__ b_ih, const float* __restrict__ b_hh)
{
    extern __shared__ __align__(16) char psm[];
    u64t*  Xs = reinterpret_cast<u64t*>(psm);            // [kk][66]
    float* Ws = reinterpret_cast<float*>(psm + 33792);   // [kk][132]
    const int gt = blockIdx.x;
    const int t  = blockIdx.y;
    const int tid = threadIdx.x;
    const int gy = tid >> 4;
    const int bx = tid & 15;

    const float* xb = x + (size_t)t * Bn * Hn;
    const float* wb = W_ih + (size_t)(gt * 128) * Hn;

    u64t acc[8][4];
#pragma unroll
    for (int i = 0; i < 8; i++)
#pragma unroll
        for (int j = 0; j < 4; j++) acc[i][j] = 0ull;

    for (int kc = 0; kc < Hn; kc += 64) {
        {
            int bp = tid & 63;
            int kq = (tid >> 6) * 16;
            const float* r0 = xb + (size_t)(2 * bp) * Hn + kc + kq;
            const float* r1 = r0 + Hn;
#pragma unroll
            for (int q = 0; q < 4; q++) {
                float4 a = *reinterpret_cast<const float4*>(r0 + q * 4);
                float4 b4 = *reinterpret_cast<const float4*>(r1 + q * 4);
                Xs[(kq + q * 4 + 0) * 66 + bp] = pack2(a.x, b4.x);
                Xs[(kq + q * 4 + 1) * 66 + bp] = pack2(a.y, b4.y);
                Xs[(kq + q * 4 + 2) * 66 + bp] = pack2(a.z, b4.z);
                Xs[(kq + q * 4 + 3) * 66 + bp] = pack2(a.w, b4.w);
            }
        }
        {
            int g   = tid & 127;
            int kq2 = (tid >> 7) * 32;
            const float* wr = wb + (size_t)g * Hn + kc + kq2;
#pragma unroll
            for (int q = 0; q < 8; q++) {
                float4 wv = *reinterpret_cast<const float4*>(wr + q * 4);
                Ws[(kq2 + q * 4 + 0) * 132 + g] = wv.x;
                Ws[(kq2 + q * 4 + 1) * 132 + g] = wv.y;
                Ws[(kq2 + q * 4 + 2) * 132 + g] = wv.z;
                Ws[(kq2 + q * 4 + 3) * 132 + g] = wv.w;
            }
        }
        __syncthreads();
#pragma unroll
        for (int kk = 0; kk < 64; kk++) {
            ulonglong2 h01 = *reinterpret_cast<const ulonglong2*>(&Xs[kk * 66 + bx * 4]);
            ulonglong2 h23 = *reinterpret_cast<const ulonglong2*>(&Xs[kk * 66 + bx * 4 + 2]);
            float4 wa = *reinterpret_cast<const float4*>(&Ws[kk * 132 + gy * 8]);
            float4 wbv = *reinterpret_cast<const float4*>(&Ws[kk * 132 + gy * 8 + 4]);
            u64t wd[8] = { dup2(wa.x), dup2(wa.y), dup2(wa.z), dup2(wa.w),
                           dup2(wbv.x), dup2(wbv.y), dup2(wbv.z), dup2(wbv.w) };
            u64t hh[4] = { h01.x, h01.y, h23.x, h23.y };
#pragma unroll
            for (int gi = 0; gi < 8; gi++)
#pragma unroll
                for (int j = 0; j < 4; j++)
                    ffma2(acc[gi][j], hh[j], wd[gi]);
        }
        __syncthreads();
    }
#pragma unroll
    for (int gi = 0; gi < 8; gi++) {
        int g = gt * 128 + gy * 8 + gi;
        float bias = __ldg(b_ih + g) + __ldg(b_hh + g);
        float2 u0 = unpack2(acc[gi][0]);
        float2 u1 = unpack2(acc[gi][1]);
        float2 u2 = unpack2(acc[gi][2]);
        float2 u3 = unpack2(acc[gi][3]);
        float* op = g_pre0 + (size_t)t * (Gn * Bn) + (size_t)g * Bn + bx * 8;
        *reinterpret_cast<float4*>(op) =
            make_float4(u0.x + bias, u0.y + bias, u1.x + bias, u1.y + bias);
        *reinterpret_cast<float4*>(op + 4) =
            make_float4(u2.x + bias, u2.y + bias, u3.x + bias, u3.y + bias);
    }
}

// ---------------------------------------------------------------------------
// Persistent skewed recurrence, shadow-barrier order (FIXED: stage B is
// issued AFTER the barrier, so every read of h1[i-2] is ordered after all
// CTAs' EW1(i-1) by the barrier).  256 CTAs x 256 threads.
// Iter i: stageA -> phaseA -> EW0 publish h0[i] -> BARRIER ->
//         stageB -> phaseB -> EW1 publish h1[i-1] -> endsync.
// CTA: bq = blk&3 (batch quarter 32), cg = blk>>2 (4 h-cols, both layers).
// Warps (8): bsel = w&1 (16-batch), kshi = w>>1 (64-K slice).
// Lanes: cs = lane&7 (2 col-pairs), kslo = lane>>3 (16-K sub-slice).
// smem: WA 32768 | WB 16384 | stageA 32768 (partials overlay) | stageB 32768
// ---------------------------------------------------------------------------
#define SM_WA    0
#define SM_WB    32768
#define SM_STAGE 49152
#define SM_STB_OFF 32768
#define SMEM_TOTAL 114688

__global__ __launch_bounds__(256, 2) void lstm_persistent(
    const float* __restrict__ W_ih, const float* __restrict__ W_hh,
    const float* __restrict__ b_ih, const float* __restrict__ b_hh,
    float* __restrict__ out)
{
    extern __shared__ __align__(16) char smraw[];
    char* smWA   = smraw + SM_WA;
    char* smWB   = smraw + SM_WB;
    char* stage  = smraw + SM_STAGE;          // stage A; stage B = +32768
    char* partc  = smraw + SM_STAGE;          // partials overlay stage A

    const int tid  = threadIdx.x;
    const int blk  = blockIdx.x;
    const int bq   = blk & 3;
    const int cg   = blk >> 2;
    const int w    = tid >> 5;
    const int lane = tid & 31;
    const int bsel = w & 1;
    const int kshi = w >> 1;          // 0..3
    const int cs   = lane & 7;
    const int kslo = lane >> 3;       // 0..3

    // ---- weights into smem (plain floats, once) ----
    {
        int p  = tid & 15;
        int kg = tid >> 4;            // 0..15 -> 16 k each
        int gc = (p >> 2) * Hn + cg * 4 + (p & 3);
        const float* wh0 = W_hh + (size_t)gc * Hn;
        const float* wi1 = W_ih + (size_t)Gn * Hn + (size_t)gc * Hn;
        float* WA = reinterpret_cast<float*>(smWA);
#pragma unroll
        for (int j = 0; j < 16; j++) {
            int k = kg * 16 + j;
            WA[k * 32 + p * 2 + 0] = __ldg(wh0 + k);
            WA[k * 32 + p * 2 + 1] = __ldg(wi1 + k);
        }
        int c   = tid & 7;
        int kg2 = tid >> 3;           // 0..31 -> 8 k each
        int gcA = ((2 * c) >> 2) * Hn + cg * 4 + ((2 * c) & 3);
        int gcB = ((2 * c + 1) >> 2) * Hn + cg * 4 + ((2 * c + 1) & 3);
        const float* wh1a = W_hh + (size_t)Gn * Hn + (size_t)gcA * Hn;
        const float* wh1b = W_hh + (size_t)Gn * Hn + (size_t)gcB * Hn;
        float* WB = reinterpret_cast<float*>(smWB);
#pragma unroll
        for (int j = 0; j < 8; j++) {
            int k = kg2 * 8 + j;
            WB[k * 16 + c * 2 + 0] = __ldg(wh1a + k);
            WB[k * 16 + c * 2 + 1] = __ldg(wh1b + k);
        }
    }
    // elementwise identity (EW0: tid<128, EW1: tid>=128)
    const int hcl = (tid >> 5) & 3;
    const int bl  = tid & 31;
    const int hcol = cg * 4 + hcl;
    const int b = bq * 32 + bl;
    float b1s[4];
#pragma unroll
    for (int g = 0; g < 4; g++)
        b1s[g] = __ldg(b_ih + Gn + g * Hn + hcol) + __ldg(b_hh + Gn + g * Hn + hcol);

    // per-warp staging base (4 blocks of 1024B, seg-swizzled)
    char* myst = stage + w * 4096;

    // zero init h ping-pong buffers (256 CTAs x 256 threads = 65536)
    {
        int idx = blk * 256 + tid;
        reinterpret_cast<float*>(g_h0)[idx] = 0.f;
        reinterpret_cast<float*>(g_h1)[idx] = 0.f;
    }
    float creg = 0.f;

    const size_t OUT_H = (size_t)Tn * Bn * Hn;
    const size_t OUT_C = OUT_H + 2 * (size_t)Bn * Hn;

    grid_barrier();   // init + weights visible

    // swizzled read pointers (stage A; stage B = +SM_STB_OFF)
    const char* p0 = myst + kslo * 1024 + (((0 + kslo) & 3) << 4);
    const char* p1 = myst + kslo * 1024 + (((1 + kslo) & 3) << 4);
    const char* p2 = myst + kslo * 1024 + (((2 + kslo) & 3) << 4);
    const char* p3 = myst + kslo * 1024 + (((3 + kslo) & 3) << 4);

    for (int i = 0; i <= Tn; i++) {
        const int rslot = (i & 1) ^ 1;
        const int wslot = i & 1;
        const float* hA = g_h0[rslot];
        const float* hB = g_h1[rslot];

        // ===== stage A half 1 (krow 0..7 of every ksb block) =====
#pragma unroll
        for (int jj = 0; jj < 4; jj++) {
            int j = jj * 2;
            int f = lane + j * 32;
            int ksb = f >> 6, rem = f & 63;
            int krow = rem >> 2, seg = rem & 3;
            int k = kshi * 64 + ksb * 16 + krow;
            size_t so = (size_t)k * Bn + bq * 32 + bsel * 16 + seg * 4;
            cp16(myst + ksb * 1024 + krow * 64 + (((seg + ksb) & 3) << 4), hA + so);
        }
        asm volatile("cp.async.commit_group;");
        // ===== stage A half 2 (krow 8..15) =====
#pragma unroll
        for (int jj = 0; jj < 4; jj++) {
            int j = jj * 2 + 1;
            int f = lane + j * 32;
            int ksb = f >> 6, rem = f & 63;
            int krow = rem >> 2, seg = rem & 3;
            int k = kshi * 64 + ksb * 16 + krow;
            size_t so = (size_t)k * Bn + bq * 32 + bsel * 16 + seg * 4;
            cp16(myst + ksb * 1024 + krow * 64 + (((seg + ksb) & 3) << 4), hA + so);
        }
        asm volatile("cp.async.commit_group;");

        // prefetch pre0 gates (EW0 operand) while staging flies
        float pg[4] = {0.f, 0.f, 0.f, 0.f};
        if (tid < 128 && i < Tn) {
            const float* pb = g_pre0 + (size_t)i * (Gn * Bn);
#pragma unroll
            for (int g = 0; g < 4; g++)
                pg[g] = __ldg(pb + (size_t)(g * Hn + hcol) * Bn + b);
        }

        u64t acc[4][8];
#pragma unroll
        for (int r = 0; r < 4; r++)
#pragma unroll
            for (int j = 0; j < 8; j++) acc[r][j] = 0ull;

        // ===== phase A (split u<8 / u>=8 across the two stage-A groups) =====
        {
            const char* wp = smWA + (size_t)(kshi * 64 + kslo * 16) * 128 + cs * 16;
            asm volatile("cp.async.wait_group 1;");
            __syncwarp();
#pragma unroll
            for (int u = 0; u < 8; u++) {
                ulonglong2 h0v = *reinterpret_cast<const ulonglong2*>(p0 + u * 64);
                ulonglong2 h1v = *reinterpret_cast<const ulonglong2*>(p1 + u * 64);
                ulonglong2 h2v = *reinterpret_cast<const ulonglong2*>(p2 + u * 64);
                ulonglong2 h3v = *reinterpret_cast<const ulonglong2*>(p3 + u * 64);
                float4 wv = *reinterpret_cast<const float4*>(wp);
                u64t w0a = dup2(wv.x), w1a = dup2(wv.y);
                u64t w0b = dup2(wv.z), w1b = dup2(wv.w);
                u64t hh[8] = {h0v.x, h0v.y, h1v.x, h1v.y, h2v.x, h2v.y, h3v.x, h3v.y};
#pragma unroll
                for (int j = 0; j < 8; j++) {
                    ffma2(acc[0][j], hh[j], w0a);
                    ffma2(acc[2][j], hh[j], w1a);
                    ffma2(acc[1][j], hh[j], w0b);
                    ffma2(acc[3][j], hh[j], w1b);
                }
                wp += 128;
            }
            asm volatile("cp.async.wait_group 0;");
            __syncwarp();
#pragma unroll
            for (int u = 8; u < 16; u++) {
                ulonglong2 h0v = *reinterpret_cast<const ulonglong2*>(p0 + u * 64);
                ulonglong2 h1v = *reinterpret_cast<const ulonglong2*>(p1 + u * 64);
                ulonglong2 h2v = *reinterpret_cast<const ulonglong2*>(p2 + u * 64);
                ulonglong2 h3v = *reinterpret_cast<const ulonglong2*>(p3 + u * 64);
                float4 wv = *reinterpret_cast<const float4*>(wp);
                u64t w0a = dup2(wv.x), w1a = dup2(wv.y);
                u64t w0b = dup2(wv.z), w1b = dup2(wv.w);
                u64t hh[8] = {h0v.x, h0v.y, h1v.x, h1v.y, h2v.x, h2v.y, h3v.x, h3v.y};
#pragma unroll
                for (int j = 0; j < 8; j++) {
                    ffma2(acc[0][j], hh[j], w0a);
                    ffma2(acc[2][j], hh[j], w1a);
                    ffma2(acc[1][j], hh[j], w0b);
                    ffma2(acc[3][j], hh[j], w1b);
                }
                wp += 128;
            }
        }
        // ---- reduce L0 accumulators across kslo ----
#pragma unroll
        for (int r = 0; r < 2; r++)
#pragma unroll
            for (int j = 0; j < 8; j++) {
                u64t v = acc[r][j];
                v = addx2(v, (u64t)__shfl_xor_sync(0xFFFFFFFFu, v, 8));
                v = addx2(v, (u64t)__shfl_xor_sync(0xFFFFFFFFu, v, 16));
                acc[r][j] = v;
            }
        __syncthreads();   // all warps done reading stage A (partials overlay)
        if (kslo == 0) {
#pragma unroll
            for (int r = 0; r < 2; r++) {
                int row = 2 * cs + r;
                char* pb = partc + row * 528 + kshi * 128 + bsel * 64;
                reinterpret_cast<ulonglong2*>(pb)[0] = make_ulonglong2(acc[r][0], acc[r][1]);
                reinterpret_cast<ulonglong2*>(pb)[1] = make_ulonglong2(acc[r][2], acc[r][3]);
                reinterpret_cast<ulonglong2*>(pb)[2] = make_ulonglong2(acc[r][4], acc[r][5]);
                reinterpret_cast<ulonglong2*>(pb)[3] = make_ulonglong2(acc[r][6], acc[r][7]);
            }
        }
        __syncthreads();
        // ===== EW0: publish h0[i] =====
        if (tid < 128 && i < Tn) {
            float s[4];
#pragma unroll
            for (int g = 0; g < 4; g++) {
                const float* pr = reinterpret_cast<const float*>(
                    partc + (g * 4 + hcl) * 528 + bl * 4);
                s[g] = pg[g] + pr[0] + pr[32] + pr[64] + pr[96];
            }
            float cn = fsig(s[1]) * creg + fsig(s[0]) * ftanh2(s[2]);
            creg = cn;
            float hn = fsig(s[3]) * ftanh2(cn);
            __stcg(&g_h0[wslot][hcol * Bn + b], hn);
            if (i == Tn - 1) {
                out[OUT_H + (size_t)b * Hn + hcol] = hn;
                out[OUT_C + (size_t)b * Hn + hcol] = cn;
            }
        }
        // ===== THE barrier (h0[i] release; also orders EW1(i-1) globally) ====
        grid_barrier();

        // ===== stage B (h1 slice) — AFTER barrier, so h1[i-2] is complete ====
#pragma unroll
        for (int j = 0; j < 8; j++) {
            int f = lane + j * 32;
            int ksb = f >> 6, rem = f & 63;
            int krow = rem >> 2, seg = rem & 3;
            int k = kshi * 64 + ksb * 16 + krow;
            size_t so = (size_t)k * Bn + bq * 32 + bsel * 16 + seg * 4;
            cp16(myst + SM_STB_OFF + ksb * 1024 + krow * 64 + (((seg + ksb) & 3) << 4),
                 hB + so);
        }
        asm volatile("cp.async.commit_group;");
        asm volatile("cp.async.wait_group 0;");
        __syncwarp();
        // ===== phase B: L1-rec on h1 slice (accumulate into L1 accs) =====
        {
            const char* wp = smWB + (size_t)(kshi * 64 + kslo * 16) * 64 + cs * 8;
#pragma unroll
            for (int u = 0; u < 16; u++) {
                ulonglong2 h0v = *reinterpret_cast<const ulonglong2*>(p0 + SM_STB_OFF + u * 64);
                ulonglong2 h1v = *reinterpret_cast<const ulonglong2*>(p1 + SM_STB_OFF + u * 64);
                ulonglong2 h2v = *reinterpret_cast<const ulonglong2*>(p2 + SM_STB_OFF + u * 64);
                ulonglong2 h3v = *reinterpret_cast<const ulonglong2*>(p3 + SM_STB_OFF + u * 64);
                float2 wv = *reinterpret_cast<const float2*>(wp);
                u64t w2a = dup2(wv.x), w2b = dup2(wv.y);
                u64t hh[8] = {h0v.x, h0v.y, h1v.x, h1v.y, h2v.x, h2v.y, h3v.x, h3v.y};
#pragma unroll
                for (int j = 0; j < 8; j++) {
                    ffma2(acc[2][j], hh[j], w2a);
                    ffma2(acc[3][j], hh[j], w2b);
                }
                wp += 64;
            }
        }
        // ---- reduce L1 accumulators across kslo ----
#pragma unroll
        for (int r = 2; r < 4; r++)
#pragma unroll
            for (int j = 0; j < 8; j++) {
                u64t v = acc[r][j];
                v = addx2(v, (u64t)__shfl_xor_sync(0xFFFFFFFFu, v, 8));
                v = addx2(v, (u64t)__shfl_xor_sync(0xFFFFFFFFu, v, 16));
                acc[r][j] = v;
            }
        // safe: all stage-A reads finished pre-barrier; rows 16-31 disjoint from
        // rows 0-15 written earlier this iter (same region, different offsets)
        if (kslo == 0) {
#pragma unroll
            for (int r = 2; r < 4; r++) {
                int row = 16 + 2 * cs + (r - 2);
                char* pb = partc + row * 528 + kshi * 128 + bsel * 64;
                reinterpret_cast<ulonglong2*>(pb)[0] = make_ulonglong2(acc[r][0], acc[r][1]);
                reinterpret_cast<ulonglong2*>(pb)[1] = make_ulonglong2(acc[r][2], acc[r][3]);
                reinterpret_cast<ulonglong2*>(pb)[2] = make_ulonglong2(acc[r][4], acc[r][5]);
                reinterpret_cast<ulonglong2*>(pb)[3] = make_ulonglong2(acc[r][6], acc[r][7]);
            }
        }
        __syncthreads();
        // ===== EW1: publish h1[i-1] =====
        if (tid >= 128 && i >= 1) {
            const int t1 = i - 1;
            float s[4];
#pragma unroll
            for (int g = 0; g < 4; g++) {
                const float* pr = reinterpret_cast<const float*>(
                    partc + (16 + g * 4 + hcl) * 528 + bl * 4);
                s[g] = b1s[g] + pr[0] + pr[32] + pr[64] + pr[96];
            }
            float cn = fsig(s[1]) * creg + fsig(s[0]) * ftanh2(s[2]);
            creg = cn;
            float hn = fsig(s[3]) * ftanh2(cn);
            __stcg(&g_h1[wslot][hcol * Bn + b], hn);
            out[(size_t)t1 * (Bn * Hn) + (size_t)b * Hn + hcol] = hn;
            if (i == Tn) {
                out[OUT_H + (size_t)Bn * Hn + (size_t)b * Hn + hcol] = hn;
                out[OUT_C + (size_t)Bn * Hn + (size_t)b * Hn + hcol] = cn;
            }
        }
        __syncthreads();   // EW reads of partials done before next stage A writes
    }
}

extern "C" void kernel_launch(void* const* d_in, const int* in_sizes, int n_in,
                              void* d_out, int out_size) {
    (void)in_sizes; (void)n_in; (void)out_size;
    const float* x    = (const float*)d_in[0];
    const float* W_ih = (const float*)d_in[1];
    const float* W_hh = (const float*)d_in[2];
    const float* b_ih = (const float*)d_in[3];
    const float* b_hh = (const float*)d_in[4];
    float* out = (float*)d_out;

    cudaFuncSetAttribute(precompute_kernel,
                         cudaFuncAttributeMaxDynamicSharedMemorySize, PRE_SMEM);
    cudaFuncSetAttribute(lstm_persistent,
                         cudaFuncAttributeMaxDynamicSharedMemorySize, SMEM_TOTAL);

    dim3 gPre(8, 512);
    precompute_kernel<<<gPre, 256, PRE_SMEM>>>(x, W_ih, b_ih, b_hh);
    lstm_persistent<<<NBLK, 256, SMEM_TOTAL>>>(W_ih, W_hh, b_ih, b_hh, out);
}

// round 15
// speedup vs baseline: 1.2069x; 1.0407x over previous
#include <cuda_runtime.h>
#include <cstdint>

#define Tn 512
#define Bn 128
#define Hn 256
#define Gn 1024
#define NBLK 256

typedef unsigned long long u64t;

// ---------------- device scratch ----------------
__device__ float g_pre0[(size_t)Tn * Gn * Bn];   // [t][gatecol][b]
__device__ float g_h0[2][Hn * Bn];               // [pp][h][b]
__device__ float g_h1[2][Hn * Bn];
__device__ volatile unsigned g_bar_gen = 0;
__device__ unsigned g_bar_cnt = 0;

__device__ __forceinline__ float fsig(float x) {
    return __fdividef(1.0f, 1.0f + __expf(-x));
}
__device__ __forceinline__ float ftanh2(float x) {
    float e = __expf(2.0f * x);
    return 1.0f - __fdividef(2.0f, e + 1.0f);
}
// grid barrier: one gpu fence by t0 per CTA
__device__ __forceinline__ void grid_barrier() {
    __syncthreads();
    if (threadIdx.x == 0) {
        asm volatile("fence.acq_rel.gpu;" ::: "memory");
        unsigned gen = g_bar_gen;
        if (atomicAdd(&g_bar_cnt, 1u) == (unsigned)(NBLK - 1)) {
            g_bar_cnt = 0u;
            asm volatile("fence.acq_rel.gpu;" ::: "memory");
            g_bar_gen = gen + 1u;
        } else {
            while (g_bar_gen == gen) { __nanosleep(20); }
            asm volatile("fence.acq_rel.gpu;" ::: "memory");
        }
    }
    __syncthreads();
}
__device__ __forceinline__ void ffma2(u64t& d, u64t a, u64t b) {
    asm volatile("fma.rn.f32x2 %0, %1, %2, %0;" : "+l"(d) : "l"(a), "l"(b));
}
__device__ __forceinline__ u64t dup2(float w) {
    u64t r;
    asm("mov.b64 %0, {%1, %1};" : "=l"(r) : "f"(w));
    return r;
}
__device__ __forceinline__ u64t pack2(float a, float b) {
    u64t r;
    asm("mov.b64 %0, {%1, %2};" : "=l"(r) : "f"(a), "f"(b));
    return r;
}
__device__ __forceinline__ float2 unpack2(u64t v) {
    float2 r;
    asm("mov.b64 {%0, %1}, %2;" : "=f"(r.x), "=f"(r.y) : "l"(v));
    return r;
}
__device__ __forceinline__ u64t addx2(u64t a, u64t b) {
    u64t r;
    asm("add.rn.f32x2 %0, %1, %2;" : "=l"(r) : "l"(a), "l"(b));
    return r;
}
__device__ __forceinline__ void cp16(void* dst, const float* src) {
    unsigned d = (unsigned)__cvta_generic_to_shared(dst);
    asm volatile("cp.async.cg.shared.global [%0], [%1], 16;" :: "r"(d), "l"(src));
}

// ---------------------------------------------------------------------------
// Precompute: pre0[t][g][b] = b_ih0[g]+b_hh0[g] + sum_k x[t][b][k]*W_ih0[g][k]
// Tile 128g x 128b, 256 threads, thread = 8g x 8b. K-chunk 64 (4 chunks).
// NEW: X tile is register-prefetched one chunk ahead (32 regs), hiding the
// x LDG round-trip under the 64-kk FFMA2 block of the previous chunk.
// Dynamic smem: Xs u64[64][66] @0 (33792) | Ws float[64][132] @33792 (33792)
// ---------------------------------------------------------------------------
#define PRE_SMEM 67584

__global__ __launch_bounds__(256, 2) void precompute_kernel(
    const float* __restrict__ x, const float* __restrict__ W_ih,
    const float* __restrict__ b_ih, const float* __restrict__ b_hh)
{
    extern __shared__ __align__(16) char psm[];
    u64t*  Xs = reinterpret_cast<u64t*>(psm);            // [kk][66]
    float* Ws = reinterpret_cast<float*>(psm + 33792);   // [kk][132]
    const int gt = blockIdx.x;
    const int t  = blockIdx.y;
    const int tid = threadIdx.x;
    const int gy = tid >> 4;
    const int bx = tid & 15;

    const float* xb = x + (size_t)t * Bn * Hn;
    const float* wb = W_ih + (size_t)(gt * 128) * Hn;

    // X-fill identity (constant per thread)
    const int bp = tid & 63;
    const int kq = (tid >> 6) * 16;
    const float* xr0 = xb + (size_t)(2 * bp) * Hn + kq;
    const float* xr1 = xr0 + Hn;

    u64t acc[8][4];
#pragma unroll
    for (int i = 0; i < 8; i++)
#pragma unroll
        for (int j = 0; j < 4; j++) acc[i][j] = 0ull;

    // ---- prefetch chunk 0 X into registers ----
    float4 xa[4], xv[4];
#pragma unroll
    for (int q = 0; q < 4; q++) {
        xa[q] = *reinterpret_cast<const float4*>(xr0 + q * 4);
        xv[q] = *reinterpret_cast<const float4*>(xr1 + q * 4);
    }

    for (int kc = 0; kc < Hn; kc += 64) {
        {   // Xs fill from prefetched regs
#pragma unroll
            for (int q = 0; q < 4; q++) {
                Xs[(kq + q * 4 + 0) * 66 + bp] = pack2(xa[q].x, xv[q].x);
                Xs[(kq + q * 4 + 1) * 66 + bp] = pack2(xa[q].y, xv[q].y);
                Xs[(kq + q * 4 + 2) * 66 + bp] = pack2(xa[q].z, xv[q].z);
                Xs[(kq + q * 4 + 3) * 66 + bp] = pack2(xa[q].w, xv[q].w);
            }
        }
        {   // Ws fill: thread -> g, 32 k values (plain floats)
            int g   = tid & 127;
            int kq2 = (tid >> 7) * 32;
            const float* wr = wb + (size_t)g * Hn + kc + kq2;
#pragma unroll
            for (int q = 0; q < 8; q++) {
                float4 wv = *reinterpret_cast<const float4*>(wr + q * 4);
                Ws[(kq2 + q * 4 + 0) * 132 + g] = wv.x;
                Ws[(kq2 + q * 4 + 1) * 132 + g] = wv.y;
                Ws[(kq2 + q * 4 + 2) * 132 + g] = wv.z;
                Ws[(kq2 + q * 4 + 3) * 132 + g] = wv.w;
            }
        }
        __syncthreads();
        // ---- issue next chunk's X loads (latency hidden under compute) ----
        if (kc + 64 < Hn) {
            const float* nr0 = xr0 + kc + 64;
            const float* nr1 = xr1 + kc + 64;
#pragma unroll
            for (int q = 0; q < 4; q++) {
                xa[q] = *reinterpret_cast<const float4*>(nr0 + q * 4);
                xv[q] = *reinterpret_cast<const float4*>(nr1 + q * 4);
            }
        }
#pragma unroll
        for (int kk = 0; kk < 64; kk++) {
            ulonglong2 h01 = *reinterpret_cast<const ulonglong2*>(&Xs[kk * 66 + bx * 4]);
            ulonglong2 h23 = *reinterpret_cast<const ulonglong2*>(&Xs[kk * 66 + bx * 4 + 2]);
            float4 wa = *reinterpret_cast<const float4*>(&Ws[kk * 132 + gy * 8]);
            float4 wbv = *reinterpret_cast<const float4*>(&Ws[kk * 132 + gy * 8 + 4]);
            u64t wd[8] = { dup2(wa.x), dup2(wa.y), dup2(wa.z), dup2(wa.w),
                           dup2(wbv.x), dup2(wbv.y), dup2(wbv.z), dup2(wbv.w) };
            u64t hh[4] = { h01.x, h01.y, h23.x, h23.y };
#pragma unroll
            for (int gi = 0; gi < 8; gi++)
#pragma unroll
                for (int j = 0; j < 4; j++)
                    ffma2(acc[gi][j], hh[j], wd[gi]);
        }
        __syncthreads();
    }
#pragma unroll
    for (int gi = 0; gi < 8; gi++) {
        int g = gt * 128 + gy * 8 + gi;
        float bias = __ldg(b_ih + g) + __ldg(b_hh + g);
        float2 u0 = unpack2(acc[gi][0]);
        float2 u1 = unpack2(acc[gi][1]);
        float2 u2 = unpack2(acc[gi][2]);
        float2 u3 = unpack2(acc[gi][3]);
        float* op = g_pre0 + (size_t)t * (Gn * Bn) + (size_t)g * Bn + bx * 8;
        *reinterpret_cast<float4*>(op) =
            make_float4(u0.x + bias, u0.y + bias, u1.x + bias, u1.y + bias);
        *reinterpret_cast<float4*>(op + 4) =
            make_float4(u2.x + bias, u2.y + bias, u3.x + bias, u3.y + bias);
    }
}

// ---------------------------------------------------------------------------
// Persistent skewed recurrence (R11 champion, verbatim). 256 CTAs x 256 thr.
// CTA: bq = blk&3 (batch quarter 32), cg = blk>>2 (4 h-cols, both layers).
// Warps (8): bsel = w&1 (16-batch), kshi = w>>1 (64-K slice).
// Lanes: cs = lane&7 (2 col-pairs), kslo = lane>>3 (16-K sub-slice).
// Dual staging buffers (A & B committed up front, swizzled, pad-free);
// partials overlay stage-A region after phases complete. One barrier/iter.
// smem: WA 32768 | WB 16384 | stageA 32768 (partials overlay) | stageB 32768
// ---------------------------------------------------------------------------
#define SM_WA    0
#define SM_WB    32768
#define SM_STAGE 49152
#define SM_STB_OFF 32768
#define SMEM_TOTAL 114688

__global__ __launch_bounds__(256, 2) void lstm_persistent(
    const float* __restrict__ W_ih, const float* __restrict__ W_hh,
    const float* __restrict__ b_ih, const float* __restrict__ b_hh,
    float* __restrict__ out)
{
    extern __shared__ __align__(16) char smraw[];
    char* smWA   = smraw + SM_WA;
    char* smWB   = smraw + SM_WB;
    char* stage  = smraw + SM_STAGE;          // stage A; stage B = +32768
    char* partc  = smraw + SM_STAGE;          // partials overlay stage A

    const int tid  = threadIdx.x;
    const int blk  = blockIdx.x;
    const int bq   = blk & 3;
    const int cg   = blk >> 2;
    const int w    = tid >> 5;
    const int lane = tid & 31;
    const int bsel = w & 1;
    const int kshi = w >> 1;          // 0..3
    const int cs   = lane & 7;
    const int kslo = lane >> 3;       // 0..3

    // ---- weights into smem (plain floats, once) ----
    {
        int p  = tid & 15;
        int kg = tid >> 4;            // 0..15 -> 16 k each
        int gc = (p >> 2) * Hn + cg * 4 + (p & 3);
        const float* wh0 = W_hh + (size_t)gc * Hn;
        const float* wi1 = W_ih + (size_t)Gn * Hn + (size_t)gc * Hn;
        float* WA = reinterpret_cast<float*>(smWA);
#pragma unroll
        for (int j = 0; j < 16; j++) {
            int k = kg * 16 + j;
            WA[k * 32 + p * 2 + 0] = __ldg(wh0 + k);
            WA[k * 32 + p * 2 + 1] = __ldg(wi1 + k);
        }
        int c   = tid & 7;
        int kg2 = tid >> 3;           // 0..31 -> 8 k each
        int gcA = ((2 * c) >> 2) * Hn + cg * 4 + ((2 * c) & 3);
        int gcB = ((2 * c + 1) >> 2) * Hn + cg * 4 + ((2 * c + 1) & 3);
        const float* wh1a = W_hh + (size_t)Gn * Hn + (size_t)gcA * Hn;
        const float* wh1b = W_hh + (size_t)Gn * Hn + (size_t)gcB * Hn;
        float* WB = reinterpret_cast<float*>(smWB);
#pragma unroll
        for (int j = 0; j < 8; j++) {
            int k = kg2 * 8 + j;
            WB[k * 16 + c * 2 + 0] = __ldg(wh1a + k);
            WB[k * 16 + c * 2 + 1] = __ldg(wh1b + k);
        }
    }
    // elementwise identity (EW0: tid<128, EW1: tid>=128)
    const int hcl = (tid >> 5) & 3;
    const int bl  = tid & 31;
    const int hcol = cg * 4 + hcl;
    const int b = bq * 32 + bl;
    float b1s[4];
#pragma unroll
    for (int g = 0; g < 4; g++)
        b1s[g] = __ldg(b_ih + Gn + g * Hn + hcol) + __ldg(b_hh + Gn + g * Hn + hcol);

    // per-warp staging base (4 blocks of 1024B, seg-swizzled)
    char* myst = stage + w * 4096;

    // zero init h ping-pong buffers (256 CTAs x 256 threads = 65536)
    {
        int idx = blk * 256 + tid;
        reinterpret_cast<float*>(g_h0)[idx] = 0.f;
        reinterpret_cast<float*>(g_h1)[idx] = 0.f;
    }
    float creg = 0.f;

    const size_t OUT_H = (size_t)Tn * Bn * Hn;
    const size_t OUT_C = OUT_H + 2 * (size_t)Bn * Hn;

    grid_barrier();   // init + weights visible

    // swizzled read pointers (stage A; stage B = +SM_STB_OFF)
    const char* p0 = myst + kslo * 1024 + (((0 + kslo) & 3) << 4);
    const char* p1 = myst + kslo * 1024 + (((1 + kslo) & 3) << 4);
    const char* p2 = myst + kslo * 1024 + (((2 + kslo) & 3) << 4);
    const char* p3 = myst + kslo * 1024 + (((3 + kslo) & 3) << 4);

    for (int i = 0; i <= Tn; i++) {
        const int rslot = (i & 1) ^ 1;
        const int wslot = i & 1;
        const float* hA = g_h0[rslot];
        const float* hB = g_h1[rslot];

        // ===== stage A (h0) and stage B (h1), both up front, swizzled =====
#pragma unroll
        for (int j = 0; j < 8; j++) {
            int f = lane + j * 32;
            int ksb = f >> 6, rem = f & 63;
            int krow = rem >> 2, seg = rem & 3;
            int k = kshi * 64 + ksb * 16 + krow;
            size_t so = (size_t)k * Bn + bq * 32 + bsel * 16 + seg * 4;
            cp16(myst + ksb * 1024 + krow * 64 + (((seg + ksb) & 3) << 4), hA + so);
        }
        asm volatile("cp.async.commit_group;");
#pragma unroll
        for (int j = 0; j < 8; j++) {
            int f = lane + j * 32;
            int ksb = f >> 6, rem = f & 63;
            int krow = rem >> 2, seg = rem & 3;
            int k = kshi * 64 + ksb * 16 + krow;
            size_t so = (size_t)k * Bn + bq * 32 + bsel * 16 + seg * 4;
            cp16(myst + SM_STB_OFF + ksb * 1024 + krow * 64 + (((seg + ksb) & 3) << 4),
                 hB + so);
        }
        asm volatile("cp.async.commit_group;");

        // prefetch pre0 gates (EW0 operand) while staging flies
        float pg[4] = {0.f, 0.f, 0.f, 0.f};
        if (tid < 128 && i < Tn) {
            const float* pb = g_pre0 + (size_t)i * (Gn * Bn);
#pragma unroll
            for (int g = 0; g < 4; g++)
                pg[g] = __ldg(pb + (size_t)(g * Hn + hcol) * Bn + b);
        }

        u64t acc[4][8];
#pragma unroll
        for (int r = 0; r < 4; r++)
#pragma unroll
            for (int j = 0; j < 8; j++) acc[r][j] = 0ull;

        asm volatile("cp.async.wait_group 1;");
        __syncwarp();
        // ===== phase A: L0-rec + L1-input on h0 slice =====
        {
            const char* wp = smWA + (size_t)(kshi * 64 + kslo * 16) * 128 + cs * 16;
#pragma unroll
            for (int u = 0; u < 16; u++) {
                ulonglong2 h0v = *reinterpret_cast<const ulonglong2*>(p0 + u * 64);
                ulonglong2 h1v = *reinterpret_cast<const ulonglong2*>(p1 + u * 64);
                ulonglong2 h2v = *reinterpret_cast<const ulonglong2*>(p2 + u * 64);
                ulonglong2 h3v = *reinterpret_cast<const ulonglong2*>(p3 + u * 64);
                float4 wv = *reinterpret_cast<const float4*>(wp);
                u64t w0a = dup2(wv.x), w1a = dup2(wv.y);
                u64t w0b = dup2(wv.z), w1b = dup2(wv.w);
                u64t hh[8] = {h0v.x, h0v.y, h1v.x, h1v.y, h2v.x, h2v.y, h3v.x, h3v.y};
#pragma unroll
                for (int j = 0; j < 8; j++) {
                    ffma2(acc[0][j], hh[j], w0a);
                    ffma2(acc[2][j], hh[j], w1a);
                    ffma2(acc[1][j], hh[j], w0b);
                    ffma2(acc[3][j], hh[j], w1b);
                }
                wp += 128;
            }
        }
        asm volatile("cp.async.wait_group 0;");
        __syncwarp();
        // ===== phase B: L1-rec on h1 slice (accumulate into L1 accs) =====
        {
            const char* wp = smWB + (size_t)(kshi * 64 + kslo * 16) * 64 + cs * 8;
#pragma unroll
            for (int u = 0; u < 16; u++) {
                ulonglong2 h0v = *reinterpret_cast<const ulonglong2*>(p0 + SM_STB_OFF + u * 64);
                ulonglong2 h1v = *reinterpret_cast<const ulonglong2*>(p1 + SM_STB_OFF + u * 64);
                ulonglong2 h2v = *reinterpret_cast<const ulonglong2*>(p2 + SM_STB_OFF + u * 64);
                ulonglong2 h3v = *reinterpret_cast<const ulonglong2*>(p3 + SM_STB_OFF + u * 64);
                float2 wv = *reinterpret_cast<const float2*>(wp);
                u64t w2a = dup2(wv.x), w2b = dup2(wv.y);
                u64t hh[8] = {h0v.x, h0v.y, h1v.x, h1v.y, h2v.x, h2v.y, h3v.x, h3v.y};
#pragma unroll
                for (int j = 0; j < 8; j++) {
                    ffma2(acc[2][j], hh[j], w2a);
                    ffma2(acc[3][j], hh[j], w2b);
                }
                wp += 64;
            }
        }

        // ===== in-warp reduce over kslo (xor 8, xor 16) =====
#pragma unroll
        for (int r = 0; r < 4; r++)
#pragma unroll
            for (int j = 0; j < 8; j++) {
                u64t v = acc[r][j];
                v = addx2(v, (u64t)__shfl_xor_sync(0xFFFFFFFFu, v, 8));
                v = addx2(v, (u64t)__shfl_xor_sync(0xFFFFFFFFu, v, 16));
                acc[r][j] = v;
            }
        // all warps must finish reading stage A before partials overlay it
        __syncthreads();
        if (kslo == 0) {
#pragma unroll
            for (int r = 0; r < 4; r++) {
                int row = (r < 2) ? (2 * cs + r) : (16 + 2 * cs + (r - 2));
                char* pb = partc + row * 528 + kshi * 128 + bsel * 64;
                reinterpret_cast<ulonglong2*>(pb)[0] = make_ulonglong2(acc[r][0], acc[r][1]);
                reinterpret_cast<ulonglong2*>(pb)[1] = make_ulonglong2(acc[r][2], acc[r][3]);
                reinterpret_cast<ulonglong2*>(pb)[2] = make_ulonglong2(acc[r][4], acc[r][5]);
                reinterpret_cast<ulonglong2*>(pb)[3] = make_ulonglong2(acc[r][6], acc[r][7]);
            }
        }
        __syncthreads();

        // ===== elementwise (sum 4 kshi partials) =====
        if (tid < 128) {
            if (i < Tn) {
                float s[4];
#pragma unroll
                for (int g = 0; g < 4; g++) {
                    const float* pr = reinterpret_cast<const float*>(
                        partc + (g * 4 + hcl) * 528 + bl * 4);
                    s[g] = pg[g] + pr[0] + pr[32] + pr[64] + pr[96];
                }
                float cn = fsig(s[1]) * creg + fsig(s[0]) * ftanh2(s[2]);
                creg = cn;
                float hn = fsig(s[3]) * ftanh2(cn);
                __stcg(&g_h0[wslot][hcol * Bn + b], hn);
                if (i == Tn - 1) {
                    out[OUT_H + (size_t)b * Hn + hcol] = hn;
                    out[OUT_C + (size_t)b * Hn + hcol] = cn;
                }
            }
        } else {
            if (i >= 1) {
                const int t1 = i - 1;
                float s[4];
#pragma unroll
                for (int g = 0; g < 4; g++) {
                    const float* pr = reinterpret_cast<const float*>(
                        partc + (16 + g * 4 + hcl) * 528 + bl * 4);
                    s[g] = b1s[g] + pr[0] + pr[32] + pr[64] + pr[96];
                }
                float cn = fsig(s[1]) * creg + fsig(s[0]) * ftanh2(s[2]);
                creg = cn;
                float hn = fsig(s[3]) * ftanh2(cn);
                __stcg(&g_h1[wslot][hcol * Bn + b], hn);
                out[(size_t)t1 * (Bn * Hn) + (size_t)b * Hn + hcol] = hn;
                if (i == Tn) {
                    out[OUT_H + (size_t)Bn * Hn + (size_t)b * Hn + hcol] = hn;
                    out[OUT_C + (size_t)Bn * Hn + (size_t)b * Hn + hcol] = cn;
                }
            }
        }
        grid_barrier();
    }
}

extern "C" void kernel_launch(void* const* d_in, const int* in_sizes, int n_in,
                              void* d_out, int out_size) {
    (void)in_sizes; (void)n_in; (void)out_size;
    const float* x    = (const float*)d_in[0];
    const float* W_ih = (const float*)d_in[1];
    const float* W_hh = (const float*)d_in[2];
    const float* b_ih = (const float*)d_in[3];
    const float* b_hh = (const float*)d_in[4];
    float* out = (float*)d_out;

    cudaFuncSetAttribute(precompute_kernel,
                         cudaFuncAttributeMaxDynamicSharedMemorySize, PRE_SMEM);
    cudaFuncSetAttribute(lstm_persistent,
                         cudaFuncAttributeMaxDynamicSharedMemorySize, SMEM_TOTAL);

    dim3 gPre(8, 512);
    precompute_kernel<<<gPre, 256, PRE_SMEM>>>(x, W_ih, b_ih, b_hh);
    lstm_persistent<<<NBLK, 256, SMEM_TOTAL>>>(W_ih, W_hh, b_ih, b_hh, out);
}